// round 1
// baseline (speedup 1.0000x reference)
#include <cuda_runtime.h>

#define NUM_NODE 50000
#define NUM_EDGE 25000
#define NNZ      800000
#define D        128

// ---------------- scratch (static device globals; no allocation) ----------
__device__ float g_X [NUM_NODE * D];   // input @ weight
__device__ float g_Xe[NUM_EDGE * D];   // edge features
__device__ int g_ecnt[NUM_EDGE];
__device__ int g_vcnt[NUM_NODE];
__device__ int g_eoff[NUM_EDGE + 1];
__device__ int g_voff[NUM_NODE + 1];
__device__ int g_ecur[NUM_EDGE];
__device__ int g_vcur[NUM_NODE];
__device__ int g_enodes[NNZ];   // edge-CSR payload: node id V[i]
__device__ int g_vedges[NNZ];   // node-CSR payload: edge id E[i]

// ---------------- zero counts ---------------------------------------------
__global__ void zero_kernel() {
    int i = blockIdx.x * blockDim.x + threadIdx.x;
    if (i < NUM_NODE) g_vcnt[i] = 0;
    if (i < NUM_EDGE) g_ecnt[i] = 0;
}

// ---------------- GEMM: X = input @ weight --------------------------------
// 128 threads/block, 16 rows/block, K tiled by 32. Thread t owns out column t.
__global__ __launch_bounds__(128) void gemm_kernel(const float* __restrict__ in,
                                                   const float* __restrict__ w) {
    __shared__ float ws[32 * D];     // weight K-tile [32][128]
    __shared__ float rs[16 * D];     // input rows   [16][128]
    int t = threadIdx.x;
    int row0 = blockIdx.x * 16;

    #pragma unroll
    for (int i = t; i < 16 * D; i += 128) rs[i] = in[row0 * D + i];

    float acc[16];
    #pragma unroll
    for (int r = 0; r < 16; r++) acc[r] = 0.f;

    for (int kt = 0; kt < 4; kt++) {
        __syncthreads();
        #pragma unroll
        for (int i = t; i < 32 * D; i += 128) ws[i] = w[kt * 32 * D + i];
        __syncthreads();
        #pragma unroll
        for (int r = 0; r < 16; r++) {
            float a = 0.f;
            #pragma unroll
            for (int k = 0; k < 32; k++)
                a += rs[r * D + kt * 32 + k] * ws[k * D + t];
            acc[r] += a;
        }
    }
    #pragma unroll
    for (int r = 0; r < 16; r++) g_X[(row0 + r) * D + t] = acc[r];
}

// ---------------- histogram -----------------------------------------------
__global__ void hist_kernel(const int* __restrict__ V, const int* __restrict__ E) {
    int i = blockIdx.x * blockDim.x + threadIdx.x;
    if (i < NNZ) {
        atomicAdd(&g_ecnt[E[i]], 1);
        atomicAdd(&g_vcnt[V[i]], 1);
    }
}

// ---------------- single-block exclusive scan (shuffle-based) --------------
// which==0 -> edges, which==1 -> nodes
__global__ __launch_bounds__(1024) void scan_kernel(int which) {
    const int* cnt = which ? g_vcnt : g_ecnt;
    int*       off = which ? g_voff : g_eoff;
    int*       cur = which ? g_vcur : g_ecur;
    const int  n   = which ? NUM_NODE : NUM_EDGE;

    __shared__ int warp_sums[32];
    __shared__ int s_carry;
    int t = threadIdx.x, lane = t & 31, wid = t >> 5;
    if (t == 0) s_carry = 0;
    __syncthreads();

    for (int base = 0; base < n; base += 1024) {
        int i = base + t;
        int v = (i < n) ? cnt[i] : 0;
        int x = v;
        #pragma unroll
        for (int d = 1; d < 32; d <<= 1) {
            int y = __shfl_up_sync(0xFFFFFFFFu, x, d);
            if (lane >= d) x += y;
        }
        if (lane == 31) warp_sums[wid] = x;
        __syncthreads();
        if (wid == 0) {
            int wv = warp_sums[lane];
            #pragma unroll
            for (int d = 1; d < 32; d <<= 1) {
                int y = __shfl_up_sync(0xFFFFFFFFu, wv, d);
                if (lane >= d) wv += y;
            }
            warp_sums[lane] = wv;
        }
        __syncthreads();
        int warp_excl = (wid == 0) ? 0 : warp_sums[wid - 1];
        int excl = s_carry + warp_excl + x - v;
        if (i < n) { off[i] = excl; cur[i] = excl; }
        int chunk_total = warp_sums[31];
        __syncthreads();
        if (t == 0) s_carry += chunk_total;
        __syncthreads();
    }
    if (threadIdx.x == 0) off[n] = s_carry;
}

// ---------------- scatter into CSR buckets --------------------------------
__global__ void scatter_kernel(const int* __restrict__ V, const int* __restrict__ E) {
    int i = blockIdx.x * blockDim.x + threadIdx.x;
    if (i < NNZ) {
        int e = E[i], v = V[i];
        int pe = atomicAdd(&g_ecur[e], 1);
        g_enodes[pe] = v;                  // store partner directly (kills one hop)
        int pv = atomicAdd(&g_vcur[v], 1);
        g_vedges[pv] = e;
    }
}

// ---------------- warp-per-edge mean of gathered node rows ----------------
__device__ __forceinline__ void acc4(float4& a, const float4& b) {
    a.x += b.x; a.y += b.y; a.z += b.z; a.w += b.w;
}

__global__ __launch_bounds__(256) void edge_mean_kernel() {
    int gw   = (blockIdx.x * blockDim.x + threadIdx.x) >> 5;
    int lane = threadIdx.x & 31;
    if (gw >= NUM_EDGE) return;
    int start = g_eoff[gw];
    int end   = g_eoff[gw + 1];
    int cnt   = end - start;

    float4 acc = make_float4(0.f, 0.f, 0.f, 0.f);
    int j = start;
    for (; j + 4 <= end; j += 4) {
        int n0 = g_enodes[j], n1 = g_enodes[j + 1];
        int n2 = g_enodes[j + 2], n3 = g_enodes[j + 3];
        float4 a0 = *((const float4*)&g_X[(size_t)n0 * D] + lane);
        float4 a1 = *((const float4*)&g_X[(size_t)n1 * D] + lane);
        float4 a2 = *((const float4*)&g_X[(size_t)n2 * D] + lane);
        float4 a3 = *((const float4*)&g_X[(size_t)n3 * D] + lane);
        acc4(acc, a0); acc4(acc, a1); acc4(acc, a2); acc4(acc, a3);
    }
    for (; j < end; j++) {
        int n0 = g_enodes[j];
        float4 a0 = *((const float4*)&g_X[(size_t)n0 * D] + lane);
        acc4(acc, a0);
    }
    float s = (cnt > 0) ? (1.0f / (float)cnt) : 0.f;
    float4 r = make_float4(acc.x * s, acc.y * s, acc.z * s, acc.w * s);
    *((float4*)&g_Xe[(size_t)gw * D] + lane) = r;
}

// ---------------- warp-per-node mean of gathered edge rows + bias ---------
__global__ __launch_bounds__(256) void node_mean_kernel(const float* __restrict__ bias,
                                                        float* __restrict__ out) {
    int gw   = (blockIdx.x * blockDim.x + threadIdx.x) >> 5;
    int lane = threadIdx.x & 31;
    if (gw >= NUM_NODE) return;
    int start = g_voff[gw];
    int end   = g_voff[gw + 1];
    int cnt   = end - start;

    float4 acc = make_float4(0.f, 0.f, 0.f, 0.f);
    int j = start;
    for (; j + 4 <= end; j += 4) {
        int e0 = g_vedges[j], e1 = g_vedges[j + 1];
        int e2 = g_vedges[j + 2], e3 = g_vedges[j + 3];
        float4 a0 = *((const float4*)&g_Xe[(size_t)e0 * D] + lane);
        float4 a1 = *((const float4*)&g_Xe[(size_t)e1 * D] + lane);
        float4 a2 = *((const float4*)&g_Xe[(size_t)e2 * D] + lane);
        float4 a3 = *((const float4*)&g_Xe[(size_t)e3 * D] + lane);
        acc4(acc, a0); acc4(acc, a1); acc4(acc, a2); acc4(acc, a3);
    }
    for (; j < end; j++) {
        int e0 = g_vedges[j];
        float4 a0 = *((const float4*)&g_Xe[(size_t)e0 * D] + lane);
        acc4(acc, a0);
    }
    float s = (cnt > 0) ? (1.0f / (float)cnt) : 0.f;
    float4 b = *((const float4*)bias + lane);
    float4 r = make_float4(acc.x * s + b.x, acc.y * s + b.y,
                           acc.z * s + b.z, acc.w * s + b.w);
    *((float4*)&out[(size_t)gw * D] + lane) = r;
}

// ---------------- launch ---------------------------------------------------
extern "C" void kernel_launch(void* const* d_in, const int* in_sizes, int n_in,
                              void* d_out, int out_size) {
    const float* input  = (const float*)d_in[0];   // [50000,128]
    const float* weight = (const float*)d_in[1];   // [128,128]
    const float* bias   = (const float*)d_in[2];   // [128]
    const int*   V      = (const int*)d_in[3];     // [800000]
    const int*   E      = (const int*)d_in[4];     // [800000]
    float*       out    = (float*)d_out;           // [50000,128]

    (void)in_sizes; (void)n_in; (void)out_size;

    zero_kernel<<<(NUM_NODE + 255) / 256, 256>>>();
    gemm_kernel<<<NUM_NODE / 16, 128>>>(input, weight);
    hist_kernel<<<(NNZ + 255) / 256, 256>>>(V, E);
    scan_kernel<<<1, 1024>>>(0);   // edges
    scan_kernel<<<1, 1024>>>(1);   // nodes
    scatter_kernel<<<(NNZ + 255) / 256, 256>>>(V, E);
    edge_mean_kernel<<<(NUM_EDGE * 32 + 255) / 256, 256>>>();
    node_mean_kernel<<<(NUM_NODE * 32 + 255) / 256, 256>>>(bias, out);
}

// round 2
// speedup vs baseline: 1.3492x; 1.3492x over previous
#include <cuda_runtime.h>

#define NUM_NODE 50000
#define NUM_EDGE 25000
#define NNZ      800000
#define D        128
#define NSEG     (NUM_EDGE + NUM_NODE)          // 75000 segments (edges then nodes)
#define SCAN_BLK 1024
#define NBLK     ((NSEG + SCAN_BLK - 1) / SCAN_BLK)   // 74

// ---------------- scratch (static device globals; no allocation) ----------
__device__ float g_X [NUM_NODE * D];   // input @ weight
__device__ float g_Xe[NUM_EDGE * D];   // edge features
__device__ int g_cnt[NSEG];            // per-segment counts (edges | nodes)
__device__ int g_off[NSEG + 1];        // CSR offsets over combined payload
__device__ int g_cur[NSEG];            // scatter cursors
__device__ int g_bsum[NBLK];           // per-block sums for scan
__device__ int g_boff[NBLK + 1];       // per-block offsets
__device__ int g_pl[2 * NNZ];          // payload: partner ids (node id for edge
                                       // buckets, edge id for node buckets)

// ---------------- zero counts ---------------------------------------------
__global__ void zero_kernel() {
    int i = blockIdx.x * blockDim.x + threadIdx.x;
    if (i < NSEG) g_cnt[i] = 0;
}

// ---------------- GEMM: X = input @ weight --------------------------------
// 128 threads/block, 16 rows/block, K tiled by 32.
// Thread t owns output column t; weight column cached in 32 registers per tile.
__global__ __launch_bounds__(128) void gemm_kernel(const float* __restrict__ in,
                                                   const float* __restrict__ w) {
    __shared__ float ws[32 * D];     // weight K-tile [32][128]
    __shared__ float rs[16 * D];     // input rows   [16][128]
    int t = threadIdx.x;
    int row0 = blockIdx.x * 16;

    // load 16 input rows (float4, coalesced)
    {
        const float4* src = (const float4*)(in + (size_t)row0 * D);
        float4* dst = (float4*)rs;
        #pragma unroll
        for (int i = 0; i < 4; i++) dst[t + 128 * i] = src[t + 128 * i];
    }

    float acc[16];
    #pragma unroll
    for (int r = 0; r < 16; r++) acc[r] = 0.f;

    #pragma unroll
    for (int kt = 0; kt < 4; kt++) {
        __syncthreads();
        {
            const float4* src = (const float4*)(w + (size_t)kt * 32 * D);
            float4* dst = (float4*)ws;
            #pragma unroll
            for (int i = 0; i < 8; i++) dst[t + 128 * i] = src[t + 128 * i];
        }
        __syncthreads();

        // cache this thread's weight column for the 32-K tile
        float wreg[32];
        #pragma unroll
        for (int k = 0; k < 32; k++) wreg[k] = ws[k * D + t];

        #pragma unroll
        for (int r = 0; r < 16; r++) {
            const float4* rrow = (const float4*)&rs[r * D + kt * 32];
            #pragma unroll
            for (int k4 = 0; k4 < 8; k4++) {
                float4 a = rrow[k4];          // broadcast load (1 crossbar phase)
                acc[r] += a.x * wreg[k4 * 4 + 0];
                acc[r] += a.y * wreg[k4 * 4 + 1];
                acc[r] += a.z * wreg[k4 * 4 + 2];
                acc[r] += a.w * wreg[k4 * 4 + 3];
            }
        }
    }
    #pragma unroll
    for (int r = 0; r < 16; r++) g_X[(size_t)(row0 + r) * D + t] = acc[r];
}

// ---------------- histogram (combined segment space) -----------------------
__global__ void hist_kernel(const int* __restrict__ V, const int* __restrict__ E) {
    int i = blockIdx.x * blockDim.x + threadIdx.x;
    if (i < NNZ) {
        atomicAdd(&g_cnt[E[i]], 1);
        atomicAdd(&g_cnt[NUM_EDGE + V[i]], 1);
    }
}

// ---------------- two-level scan ------------------------------------------
// pass 1: per-block reduction
__global__ __launch_bounds__(SCAN_BLK) void scan_reduce_kernel() {
    __shared__ int wsum[32];
    int t = threadIdx.x, lane = t & 31, wid = t >> 5;
    int i = blockIdx.x * SCAN_BLK + t;
    int v = (i < NSEG) ? g_cnt[i] : 0;
    #pragma unroll
    for (int d = 16; d > 0; d >>= 1) v += __shfl_down_sync(0xFFFFFFFFu, v, d);
    if (lane == 0) wsum[wid] = v;
    __syncthreads();
    if (wid == 0) {
        int x = wsum[lane];
        #pragma unroll
        for (int d = 16; d > 0; d >>= 1) x += __shfl_down_sync(0xFFFFFFFFu, x, d);
        if (lane == 0) g_bsum[blockIdx.x] = x;
    }
}

// pass 2: scan the NBLK block sums (single tiny block)
__global__ __launch_bounds__(128) void scan_mid_kernel() {
    __shared__ int wsum[4];
    int t = threadIdx.x, lane = t & 31, wid = t >> 5;
    int v = (t < NBLK) ? g_bsum[t] : 0;
    int x = v;
    #pragma unroll
    for (int d = 1; d < 32; d <<= 1) {
        int y = __shfl_up_sync(0xFFFFFFFFu, x, d);
        if (lane >= d) x += y;
    }
    if (lane == 31) wsum[wid] = x;
    __syncthreads();
    int carry = 0;
    for (int wprev = 0; wprev < wid; wprev++) carry += wsum[wprev];
    int excl = carry + x - v;
    if (t < NBLK) g_boff[t] = excl;
    if (t == NBLK - 1) {
        g_boff[NBLK] = excl + v;
        g_off[NSEG]  = excl + v;     // grand total = 2*NNZ
    }
}

// pass 3: re-scan each block, add block offset, emit off + cur
__global__ __launch_bounds__(SCAN_BLK) void scan_apply_kernel() {
    __shared__ int wsum[32];
    int t = threadIdx.x, lane = t & 31, wid = t >> 5;
    int i = blockIdx.x * SCAN_BLK + t;
    int v = (i < NSEG) ? g_cnt[i] : 0;
    int x = v;
    #pragma unroll
    for (int d = 1; d < 32; d <<= 1) {
        int y = __shfl_up_sync(0xFFFFFFFFu, x, d);
        if (lane >= d) x += y;
    }
    if (lane == 31) wsum[wid] = x;
    __syncthreads();
    if (wid == 0) {
        int wv = wsum[lane];
        #pragma unroll
        for (int d = 1; d < 32; d <<= 1) {
            int y = __shfl_up_sync(0xFFFFFFFFu, wv, d);
            if (lane >= d) wv += y;
        }
        wsum[lane] = wv;
    }
    __syncthreads();
    int warp_excl = (wid == 0) ? 0 : wsum[wid - 1];
    int excl = g_boff[blockIdx.x] + warp_excl + x - v;
    if (i < NSEG) { g_off[i] = excl; g_cur[i] = excl; }
}

// ---------------- scatter into CSR buckets --------------------------------
__global__ void scatter_kernel(const int* __restrict__ V, const int* __restrict__ E) {
    int i = blockIdx.x * blockDim.x + threadIdx.x;
    if (i < NNZ) {
        int e = E[i], v = V[i];
        int pe = atomicAdd(&g_cur[e], 1);
        g_pl[pe] = v;                         // edge bucket stores node id
        int pv = atomicAdd(&g_cur[NUM_EDGE + v], 1);
        g_pl[pv] = e;                         // node bucket stores edge id
    }
}

// ---------------- warp-per-edge mean of gathered node rows ----------------
__device__ __forceinline__ void acc4(float4& a, const float4& b) {
    a.x += b.x; a.y += b.y; a.z += b.z; a.w += b.w;
}

__global__ __launch_bounds__(256) void edge_mean_kernel() {
    int gw   = (blockIdx.x * blockDim.x + threadIdx.x) >> 5;
    int lane = threadIdx.x & 31;
    if (gw >= NUM_EDGE) return;
    int start = g_off[gw];
    int end   = g_off[gw + 1];
    int cnt   = end - start;

    float4 acc = make_float4(0.f, 0.f, 0.f, 0.f);
    int j = start;
    for (; j + 4 <= end; j += 4) {
        int n0 = g_pl[j], n1 = g_pl[j + 1];
        int n2 = g_pl[j + 2], n3 = g_pl[j + 3];
        float4 a0 = *((const float4*)&g_X[(size_t)n0 * D] + lane);
        float4 a1 = *((const float4*)&g_X[(size_t)n1 * D] + lane);
        float4 a2 = *((const float4*)&g_X[(size_t)n2 * D] + lane);
        float4 a3 = *((const float4*)&g_X[(size_t)n3 * D] + lane);
        acc4(acc, a0); acc4(acc, a1); acc4(acc, a2); acc4(acc, a3);
    }
    for (; j < end; j++) {
        int n0 = g_pl[j];
        float4 a0 = *((const float4*)&g_X[(size_t)n0 * D] + lane);
        acc4(acc, a0);
    }
    float s = (cnt > 0) ? (1.0f / (float)cnt) : 0.f;
    float4 r = make_float4(acc.x * s, acc.y * s, acc.z * s, acc.w * s);
    *((float4*)&g_Xe[(size_t)gw * D] + lane) = r;
}

// ---------------- warp-per-node mean of gathered edge rows + bias ---------
__global__ __launch_bounds__(256) void node_mean_kernel(const float* __restrict__ bias,
                                                        float* __restrict__ out) {
    int gw   = (blockIdx.x * blockDim.x + threadIdx.x) >> 5;
    int lane = threadIdx.x & 31;
    if (gw >= NUM_NODE) return;
    int start = g_off[NUM_EDGE + gw];
    int end   = g_off[NUM_EDGE + gw + 1];
    int cnt   = end - start;

    float4 acc = make_float4(0.f, 0.f, 0.f, 0.f);
    int j = start;
    for (; j + 4 <= end; j += 4) {
        int e0 = g_pl[j], e1 = g_pl[j + 1];
        int e2 = g_pl[j + 2], e3 = g_pl[j + 3];
        float4 a0 = *((const float4*)&g_Xe[(size_t)e0 * D] + lane);
        float4 a1 = *((const float4*)&g_Xe[(size_t)e1 * D] + lane);
        float4 a2 = *((const float4*)&g_Xe[(size_t)e2 * D] + lane);
        float4 a3 = *((const float4*)&g_Xe[(size_t)e3 * D] + lane);
        acc4(acc, a0); acc4(acc, a1); acc4(acc, a2); acc4(acc, a3);
    }
    for (; j < end; j++) {
        int e0 = g_pl[j];
        float4 a0 = *((const float4*)&g_Xe[(size_t)e0 * D] + lane);
        acc4(acc, a0);
    }
    float s = (cnt > 0) ? (1.0f / (float)cnt) : 0.f;
    float4 b = *((const float4*)bias + lane);
    float4 r = make_float4(acc.x * s + b.x, acc.y * s + b.y,
                           acc.z * s + b.z, acc.w * s + b.w);
    *((float4*)&out[(size_t)gw * D] + lane) = r;
}

// ---------------- launch ---------------------------------------------------
extern "C" void kernel_launch(void* const* d_in, const int* in_sizes, int n_in,
                              void* d_out, int out_size) {
    const float* input  = (const float*)d_in[0];   // [50000,128]
    const float* weight = (const float*)d_in[1];   // [128,128]
    const float* bias   = (const float*)d_in[2];   // [128]
    const int*   V      = (const int*)d_in[3];     // [800000]
    const int*   E      = (const int*)d_in[4];     // [800000]
    float*       out    = (float*)d_out;           // [50000,128]

    (void)in_sizes; (void)n_in; (void)out_size;

    zero_kernel<<<(NSEG + 255) / 256, 256>>>();
    gemm_kernel<<<NUM_NODE / 16, 128>>>(input, weight);
    hist_kernel<<<(NNZ + 255) / 256, 256>>>(V, E);
    scan_reduce_kernel<<<NBLK, SCAN_BLK>>>();
    scan_mid_kernel<<<1, 128>>>();
    scan_apply_kernel<<<NBLK, SCAN_BLK>>>();
    scatter_kernel<<<(NNZ + 255) / 256, 256>>>(V, E);
    edge_mean_kernel<<<(NUM_EDGE * 32 + 255) / 256, 256>>>();
    node_mean_kernel<<<(NUM_NODE * 32 + 255) / 256, 256>>>(bias, out);
}

// round 5
// speedup vs baseline: 1.5550x; 1.1525x over previous
#include <cuda_runtime.h>
#include <cuda_fp16.h>

#define NUM_NODE 50000
#define NUM_EDGE 25000
#define NNZ      800000
#define D        128
#define NSEG     (NUM_EDGE + NUM_NODE)               // 75000 segments
#define SCAN_BLK 1024
#define NBLK     ((NSEG + SCAN_BLK - 1) / SCAN_BLK)  // 74

#define HIST_BLOCKS 512
#define GEMM_BLOCKS (NUM_NODE / 16)                  // 3125 tiles of 16 rows
#define EDGE_BLOCKS (NUM_EDGE / 8)                   // 3125 (8 warps/block)
#define ZERO_BLOCKS ((NSEG + 255) / 256)             // 293
#define NODE_BLOCKS (NUM_NODE / 8)                   // 6250

// ---------------- scratch (static device globals; zero-initialized) -------
__device__ __half g_Xh [NUM_NODE * D];   // input @ weight, fp16 (12.8 MB)
__device__ __half g_Xeh[NUM_EDGE * D];   // edge features, fp16 (6.4 MB)
__device__ int g_cnt[NSEG];              // counts; re-zeroed by edge_mean tail
__device__ int g_off[NSEG + 1];
__device__ int g_cur[NSEG];
__device__ int g_bsum[NBLK];
__device__ int g_boff[NBLK + 1];
__device__ int g_pl[2 * NNZ];            // CSR payload (partner ids)

// ---------------- GEMM tile role: 128 threads, 16 rows (round-2 proven) ----
__device__ __forceinline__ void gemm_tile_role(const float* __restrict__ in,
                                               const float* __restrict__ w,
                                               int tile) {
    __shared__ float ws[32 * D];     // weight K-tile [32][128]
    __shared__ float rs[16 * D];     // input rows   [16][128]
    int t = threadIdx.x;
    int row0 = tile * 16;

    {
        const float4* src = (const float4*)(in + (size_t)row0 * D);
        float4* dst = (float4*)rs;
        #pragma unroll
        for (int i = 0; i < 4; i++) dst[t + 128 * i] = src[t + 128 * i];
    }

    float acc[16];
    #pragma unroll
    for (int r = 0; r < 16; r++) acc[r] = 0.f;

    #pragma unroll
    for (int kt = 0; kt < 4; kt++) {
        __syncthreads();
        {
            const float4* src = (const float4*)(w + (size_t)kt * 32 * D);
            float4* dst = (float4*)ws;
            #pragma unroll
            for (int i = 0; i < 8; i++) dst[t + 128 * i] = src[t + 128 * i];
        }
        __syncthreads();

        float wreg[32];
        #pragma unroll
        for (int k = 0; k < 32; k++) wreg[k] = ws[k * D + t];

        #pragma unroll
        for (int r = 0; r < 16; r++) {
            const float4* rrow = (const float4*)&rs[r * D + kt * 32];
            #pragma unroll
            for (int k4 = 0; k4 < 8; k4++) {
                float4 a = rrow[k4];       // broadcast (1 crossbar phase)
                acc[r] += a.x * wreg[k4 * 4 + 0];
                acc[r] += a.y * wreg[k4 * 4 + 1];
                acc[r] += a.z * wreg[k4 * 4 + 2];
                acc[r] += a.w * wreg[k4 * 4 + 3];
            }
        }
    }
    #pragma unroll
    for (int r = 0; r < 16; r++)
        g_Xh[(size_t)(row0 + r) * D + t] = __float2half_rn(acc[r]);
}

// ---------------- fused launch 1: hist | gemm ------------------------------
__global__ __launch_bounds__(128) void fused_hist_gemm(const int* __restrict__ V,
                                                       const int* __restrict__ E,
                                                       const float* __restrict__ in,
                                                       const float* __restrict__ w) {
    if (blockIdx.x < HIST_BLOCKS) {
        for (int i = blockIdx.x * 128 + threadIdx.x; i < NNZ; i += HIST_BLOCKS * 128) {
            atomicAdd(&g_cnt[E[i]], 1);
            atomicAdd(&g_cnt[NUM_EDGE + V[i]], 1);
        }
    } else {
        gemm_tile_role(in, w, (int)blockIdx.x - HIST_BLOCKS);
    }
}

// ---------------- two-level scan (round-2 proven) --------------------------
__global__ __launch_bounds__(SCAN_BLK) void scan_reduce_kernel() {
    __shared__ int wsum[32];
    int t = threadIdx.x, lane = t & 31, wid = t >> 5;
    int i = blockIdx.x * SCAN_BLK + t;
    int v = (i < NSEG) ? g_cnt[i] : 0;
    #pragma unroll
    for (int d = 16; d > 0; d >>= 1) v += __shfl_down_sync(0xFFFFFFFFu, v, d);
    if (lane == 0) wsum[wid] = v;
    __syncthreads();
    if (wid == 0) {
        int x = wsum[lane];
        #pragma unroll
        for (int d = 16; d > 0; d >>= 1) x += __shfl_down_sync(0xFFFFFFFFu, x, d);
        if (lane == 0) g_bsum[blockIdx.x] = x;
    }
}

__global__ __launch_bounds__(128) void scan_mid_kernel() {
    __shared__ int wsum[4];
    int t = threadIdx.x, lane = t & 31, wid = t >> 5;
    int v = (t < NBLK) ? g_bsum[t] : 0;
    int x = v;
    #pragma unroll
    for (int d = 1; d < 32; d <<= 1) {
        int y = __shfl_up_sync(0xFFFFFFFFu, x, d);
        if (lane >= d) x += y;
    }
    if (lane == 31) wsum[wid] = x;
    __syncthreads();
    int carry = 0;
    for (int wprev = 0; wprev < wid; wprev++) carry += wsum[wprev];
    int excl = carry + x - v;
    if (t < NBLK) g_boff[t] = excl;
    if (t == NBLK - 1) {
        g_boff[NBLK] = excl + v;
        g_off[NSEG]  = excl + v;     // grand total = 2*NNZ
    }
}

__global__ __launch_bounds__(SCAN_BLK) void scan_apply_kernel() {
    __shared__ int wsum[32];
    int t = threadIdx.x, lane = t & 31, wid = t >> 5;
    int i = blockIdx.x * SCAN_BLK + t;
    int v = (i < NSEG) ? g_cnt[i] : 0;
    int x = v;
    #pragma unroll
    for (int d = 1; d < 32; d <<= 1) {
        int y = __shfl_up_sync(0xFFFFFFFFu, x, d);
        if (lane >= d) x += y;
    }
    if (lane == 31) wsum[wid] = x;
    __syncthreads();
    if (wid == 0) {
        int wv = wsum[lane];
        #pragma unroll
        for (int d = 1; d < 32; d <<= 1) {
            int y = __shfl_up_sync(0xFFFFFFFFu, wv, d);
            if (lane >= d) wv += y;
        }
        wsum[lane] = wv;
    }
    __syncthreads();
    int warp_excl = (wid == 0) ? 0 : wsum[wid - 1];
    int excl = g_boff[blockIdx.x] + warp_excl + x - v;
    if (i < NSEG) { g_off[i] = excl; g_cur[i] = excl; }
}

// ---------------- scatter into CSR buckets (round-2 proven) ----------------
__global__ void scatter_kernel(const int* __restrict__ V, const int* __restrict__ E) {
    int i = blockIdx.x * blockDim.x + threadIdx.x;
    if (i < NNZ) {
        int e = E[i], v = V[i];
        int pe = atomicAdd(&g_cur[e], 1);
        g_pl[pe] = v;                         // edge bucket stores node id
        int pv = atomicAdd(&g_cur[NUM_EDGE + v], 1);
        g_pl[pv] = e;                         // node bucket stores edge id
    }
}

// ---------------- fp16 gather helper ---------------------------------------
__device__ __forceinline__ void acc_h4(float4& a, float2 raw) {
    __half2 h01 = *reinterpret_cast<__half2*>(&raw.x);
    __half2 h23 = *reinterpret_cast<__half2*>(&raw.y);
    float2 f01 = __half22float2(h01);
    float2 f23 = __half22float2(h23);
    a.x += f01.x; a.y += f01.y; a.z += f23.x; a.w += f23.y;
}

// ---------------- edge mean (fp16 in/out) | zero counts --------------------
__global__ __launch_bounds__(256) void edge_mean_zero_kernel() {
    if (blockIdx.x < EDGE_BLOCKS) {
        int gw   = blockIdx.x * 8 + (threadIdx.x >> 5);
        int lane = threadIdx.x & 31;
        int start = g_off[gw];
        int end   = g_off[gw + 1];
        int cnt   = end - start;

        float4 acc = make_float4(0.f, 0.f, 0.f, 0.f);
        int j = start;
        for (; j + 4 <= end; j += 4) {
            int n0 = g_pl[j], n1 = g_pl[j + 1];
            int n2 = g_pl[j + 2], n3 = g_pl[j + 3];
            float2 a0 = ((const float2*)(g_Xh + (size_t)n0 * D))[lane];
            float2 a1 = ((const float2*)(g_Xh + (size_t)n1 * D))[lane];
            float2 a2 = ((const float2*)(g_Xh + (size_t)n2 * D))[lane];
            float2 a3 = ((const float2*)(g_Xh + (size_t)n3 * D))[lane];
            acc_h4(acc, a0); acc_h4(acc, a1); acc_h4(acc, a2); acc_h4(acc, a3);
        }
        for (; j < end; j++) {
            float2 a0 = ((const float2*)(g_Xh + (size_t)g_pl[j] * D))[lane];
            acc_h4(acc, a0);
        }
        float s = (cnt > 0) ? (1.0f / (float)cnt) : 0.f;
        __half2 o01 = __floats2half2_rn(acc.x * s, acc.y * s);
        __half2 o23 = __floats2half2_rn(acc.z * s, acc.w * s);
        float2 st;
        *reinterpret_cast<__half2*>(&st.x) = o01;
        *reinterpret_cast<__half2*>(&st.y) = o23;
        ((float2*)(g_Xeh + (size_t)gw * D))[lane] = st;
    } else {
        // re-zero counts for the next graph replay (g_cnt dead after scan)
        int i = (blockIdx.x - EDGE_BLOCKS) * 256 + threadIdx.x;
        if (i < NSEG) g_cnt[i] = 0;
    }
}

// ---------------- node mean (fp16 in) + bias, fp32 out ---------------------
__global__ __launch_bounds__(256) void node_mean_kernel(const float* __restrict__ bias,
                                                        float* __restrict__ out) {
    int gw   = blockIdx.x * 8 + (threadIdx.x >> 5);
    int lane = threadIdx.x & 31;
    int start = g_off[NUM_EDGE + gw];
    int end   = g_off[NUM_EDGE + gw + 1];
    int cnt   = end - start;

    float4 acc = make_float4(0.f, 0.f, 0.f, 0.f);
    int j = start;
    for (; j + 4 <= end; j += 4) {
        int e0 = g_pl[j], e1 = g_pl[j + 1];
        int e2 = g_pl[j + 2], e3 = g_pl[j + 3];
        float2 a0 = ((const float2*)(g_Xeh + (size_t)e0 * D))[lane];
        float2 a1 = ((const float2*)(g_Xeh + (size_t)e1 * D))[lane];
        float2 a2 = ((const float2*)(g_Xeh + (size_t)e2 * D))[lane];
        float2 a3 = ((const float2*)(g_Xeh + (size_t)e3 * D))[lane];
        acc_h4(acc, a0); acc_h4(acc, a1); acc_h4(acc, a2); acc_h4(acc, a3);
    }
    for (; j < end; j++) {
        float2 a0 = ((const float2*)(g_Xeh + (size_t)g_pl[j] * D))[lane];
        acc_h4(acc, a0);
    }
    float s = (cnt > 0) ? (1.0f / (float)cnt) : 0.f;
    float4 b = *((const float4*)bias + lane);
    float4 r = make_float4(acc.x * s + b.x, acc.y * s + b.y,
                           acc.z * s + b.z, acc.w * s + b.w);
    *((float4*)&out[(size_t)gw * D] + lane) = r;
}

// ---------------- launch ---------------------------------------------------
extern "C" void kernel_launch(void* const* d_in, const int* in_sizes, int n_in,
                              void* d_out, int out_size) {
    const float* input  = (const float*)d_in[0];   // [50000,128]
    const float* weight = (const float*)d_in[1];   // [128,128]
    const float* bias   = (const float*)d_in[2];   // [128]
    const int*   V      = (const int*)d_in[3];     // [800000]
    const int*   E      = (const int*)d_in[4];     // [800000]
    float*       out    = (float*)d_out;           // [50000,128]

    (void)in_sizes; (void)n_in; (void)out_size;

    fused_hist_gemm   <<<HIST_BLOCKS + GEMM_BLOCKS, 128>>>(V, E, input, weight);
    scan_reduce_kernel<<<NBLK, SCAN_BLK>>>();
    scan_mid_kernel   <<<1, 128>>>();
    scan_apply_kernel <<<NBLK, SCAN_BLK>>>();
    scatter_kernel    <<<(NNZ + 255) / 256, 256>>>(V, E);
    edge_mean_zero_kernel<<<EDGE_BLOCKS + ZERO_BLOCKS, 256>>>();
    node_mean_kernel     <<<NODE_BLOCKS, 256>>>(bias, out);
}

// round 8
// speedup vs baseline: 1.6222x; 1.0432x over previous
#include <cuda_runtime.h>
#include <cuda_fp16.h>

#define NUM_NODE 50000
#define NUM_EDGE 25000
#define NNZ      800000
#define D        128
#define NSEG     (NUM_EDGE + NUM_NODE)               // 75000 segments
#define SCAN_BLK 1024
#define NBLK     ((NSEG + SCAN_BLK - 1) / SCAN_BLK)  // 74

#define HIST_BLOCKS 512
#define GEMM_BLOCKS (NUM_NODE / 16)                  // 3125 tiles of 16 rows
#define EDGE_BLOCKS (NUM_EDGE / 8)                   // 3125 (8 warps/block)
#define ZERO_BLOCKS ((NSEG + 255) / 256)             // 293
#define NODE_BLOCKS (NUM_NODE / 8)                   // 6250

// ---------------- scratch (static device globals; zero-initialized) -------
__device__ __half g_Xh [NUM_NODE * D];   // input @ weight, fp16 (12.8 MB)
__device__ __half g_Xeh[NUM_EDGE * D];   // edge features, fp16 (6.4 MB)
__device__ int g_cnt[NSEG];              // counts; re-zeroed by edge_mean tail
__device__ int g_off[NSEG + 1];
__device__ int g_bsum[NBLK];
__device__ unsigned int g_rank[NNZ];     // packed ranks: edge lo16 | node hi16
__device__ int g_pl[2 * NNZ];            // CSR payload (partner ids)

// ---------------- GEMM tile role: 128 threads, 16 rows (SINGLE instantiation)
__device__ __forceinline__ void gemm_tile_role(const float* __restrict__ in,
                                               const float* __restrict__ w,
                                               int tile) {
    __shared__ float ws[32 * D];     // weight K-tile [32][128]
    __shared__ float rs[16 * D];     // input rows   [16][128]
    int t = threadIdx.x;
    int row0 = tile * 16;

    {
        const float4* src = (const float4*)(in + (size_t)row0 * D);
        float4* dst = (float4*)rs;
        #pragma unroll
        for (int i = 0; i < 4; i++) dst[t + 128 * i] = src[t + 128 * i];
    }

    float acc[16];
    #pragma unroll
    for (int r = 0; r < 16; r++) acc[r] = 0.f;

    #pragma unroll
    for (int kt = 0; kt < 4; kt++) {
        __syncthreads();
        {
            const float4* src = (const float4*)(w + (size_t)kt * 32 * D);
            float4* dst = (float4*)ws;
            #pragma unroll
            for (int i = 0; i < 8; i++) dst[t + 128 * i] = src[t + 128 * i];
        }
        __syncthreads();

        float wreg[32];
        #pragma unroll
        for (int k = 0; k < 32; k++) wreg[k] = ws[k * D + t];

        #pragma unroll
        for (int r = 0; r < 16; r++) {
            const float4* rrow = (const float4*)&rs[r * D + kt * 32];
            #pragma unroll
            for (int k4 = 0; k4 < 8; k4++) {
                float4 a = rrow[k4];       // broadcast (1 crossbar phase)
                acc[r] += a.x * wreg[k4 * 4 + 0];
                acc[r] += a.y * wreg[k4 * 4 + 1];
                acc[r] += a.z * wreg[k4 * 4 + 2];
                acc[r] += a.w * wreg[k4 * 4 + 3];
            }
        }
    }
    #pragma unroll
    for (int r = 0; r < 16; r++)
        g_Xh[(size_t)(row0 + r) * D + t] = __float2half_rn(acc[r]);
}

// ---------------- L1: hist + ranks | gemm ----------------------------------
__global__ __launch_bounds__(128) void fused_hist_gemm(const int* __restrict__ V,
                                                       const int* __restrict__ E,
                                                       const float* __restrict__ in,
                                                       const float* __restrict__ w) {
    if (blockIdx.x < HIST_BLOCKS) {
        for (int i = blockIdx.x * 128 + threadIdx.x; i < NNZ; i += HIST_BLOCKS * 128) {
            int e = E[i], v = V[i];
            unsigned int re = (unsigned int)atomicAdd(&g_cnt[e], 1);
            unsigned int rv = (unsigned int)atomicAdd(&g_cnt[NUM_EDGE + v], 1);
            g_rank[i] = re | (rv << 16);
        }
    } else {
        gemm_tile_role(in, w, (int)blockIdx.x - HIST_BLOCKS);
    }
}

// ---------------- L2: per-block reduction ----------------------------------
__global__ __launch_bounds__(SCAN_BLK) void scan_reduce_kernel() {
    __shared__ int wsum[32];
    int t = threadIdx.x, lane = t & 31, wid = t >> 5;
    int i = blockIdx.x * SCAN_BLK + t;
    int v = (i < NSEG) ? g_cnt[i] : 0;
    #pragma unroll
    for (int d = 16; d > 0; d >>= 1) v += __shfl_down_sync(0xFFFFFFFFu, v, d);
    if (lane == 0) wsum[wid] = v;
    __syncthreads();
    if (wid == 0) {
        int x = wsum[lane];
        #pragma unroll
        for (int d = 16; d > 0; d >>= 1) x += __shfl_down_sync(0xFFFFFFFFu, x, d);
        if (lane == 0) g_bsum[blockIdx.x] = x;
    }
}

// ---------------- L3: scan + apply with inline block prefix ----------------
__global__ __launch_bounds__(SCAN_BLK) void scan_apply_kernel() {
    __shared__ int wsum[32];
    __shared__ int s_prefix;
    int t = threadIdx.x, lane = t & 31, wid = t >> 5;

    // warp 0 computes this block's global prefix from the 74 block sums
    if (wid == 0) {
        int s = 0;
        for (int i = lane; i < (int)blockIdx.x; i += 32) s += g_bsum[i];
        #pragma unroll
        for (int d = 16; d > 0; d >>= 1) s += __shfl_down_sync(0xFFFFFFFFu, s, d);
        if (lane == 0) s_prefix = s;
    }

    int i = blockIdx.x * SCAN_BLK + t;
    int v = (i < NSEG) ? g_cnt[i] : 0;
    int x = v;
    #pragma unroll
    for (int d = 1; d < 32; d <<= 1) {
        int y = __shfl_up_sync(0xFFFFFFFFu, x, d);
        if (lane >= d) x += y;
    }
    if (lane == 31) wsum[wid] = x;
    __syncthreads();
    if (wid == 0) {
        int wv = wsum[lane];
        #pragma unroll
        for (int d = 1; d < 32; d <<= 1) {
            int y = __shfl_up_sync(0xFFFFFFFFu, wv, d);
            if (lane >= d) wv += y;
        }
        wsum[lane] = wv;
    }
    __syncthreads();
    int warp_excl = (wid == 0) ? 0 : wsum[wid - 1];
    int excl = s_prefix + warp_excl + x - v;
    if (i < NSEG) g_off[i] = excl;
    if (i == NSEG - 1) g_off[NSEG] = excl + v;   // grand total = 2*NNZ
}

// ---------------- L4: rank-based scatter (NO atomics, unfused) -------------
__global__ void scatter_kernel(const int* __restrict__ V, const int* __restrict__ E) {
    int i = blockIdx.x * blockDim.x + threadIdx.x;
    if (i < NNZ) {
        int e = E[i], v = V[i];
        unsigned int r = g_rank[i];
        g_pl[g_off[e] + (int)(r & 0xFFFFu)] = v;              // edge bucket
        g_pl[g_off[NUM_EDGE + v] + (int)(r >> 16)] = e;       // node bucket
    }
}

// ---------------- fp16 gather helper ---------------------------------------
__device__ __forceinline__ void acc_h4(float4& a, float2 raw) {
    __half2 h01 = *reinterpret_cast<__half2*>(&raw.x);
    __half2 h23 = *reinterpret_cast<__half2*>(&raw.y);
    float2 f01 = __half22float2(h01);
    float2 f23 = __half22float2(h23);
    a.x += f01.x; a.y += f01.y; a.z += f23.x; a.w += f23.y;
}

// ---------------- L5: edge mean (fp16) | zero counts -----------------------
__global__ __launch_bounds__(256) void edge_mean_zero_kernel() {
    if (blockIdx.x < EDGE_BLOCKS) {
        int gw   = blockIdx.x * 8 + (threadIdx.x >> 5);
        int lane = threadIdx.x & 31;
        int start = g_off[gw];
        int end   = g_off[gw + 1];
        int cnt   = end - start;

        float4 acc = make_float4(0.f, 0.f, 0.f, 0.f);
        int j = start;
        for (; j + 4 <= end; j += 4) {
            int n0 = g_pl[j], n1 = g_pl[j + 1];
            int n2 = g_pl[j + 2], n3 = g_pl[j + 3];
            float2 a0 = ((const float2*)(g_Xh + (size_t)n0 * D))[lane];
            float2 a1 = ((const float2*)(g_Xh + (size_t)n1 * D))[lane];
            float2 a2 = ((const float2*)(g_Xh + (size_t)n2 * D))[lane];
            float2 a3 = ((const float2*)(g_Xh + (size_t)n3 * D))[lane];
            acc_h4(acc, a0); acc_h4(acc, a1); acc_h4(acc, a2); acc_h4(acc, a3);
        }
        for (; j < end; j++) {
            float2 a0 = ((const float2*)(g_Xh + (size_t)g_pl[j] * D))[lane];
            acc_h4(acc, a0);
        }
        float s = (cnt > 0) ? (1.0f / (float)cnt) : 0.f;
        __half2 o01 = __floats2half2_rn(acc.x * s, acc.y * s);
        __half2 o23 = __floats2half2_rn(acc.z * s, acc.w * s);
        float2 st;
        *reinterpret_cast<__half2*>(&st.x) = o01;
        *reinterpret_cast<__half2*>(&st.y) = o23;
        ((float2*)(g_Xeh + (size_t)gw * D))[lane] = st;
    } else {
        // re-zero counts for the next graph replay (g_cnt dead after scan)
        int i = (blockIdx.x - EDGE_BLOCKS) * 256 + threadIdx.x;
        if (i < NSEG) g_cnt[i] = 0;
    }
}

// ---------------- L6: node mean (fp16 in) + bias, fp32 out -----------------
__global__ __launch_bounds__(256) void node_mean_kernel(const float* __restrict__ bias,
                                                        float* __restrict__ out) {
    int gw   = blockIdx.x * 8 + (threadIdx.x >> 5);
    int lane = threadIdx.x & 31;
    int start = g_off[NUM_EDGE + gw];
    int end   = g_off[NUM_EDGE + gw + 1];
    int cnt   = end - start;

    float4 acc = make_float4(0.f, 0.f, 0.f, 0.f);
    int j = start;
    for (; j + 4 <= end; j += 4) {
        int e0 = g_pl[j], e1 = g_pl[j + 1];
        int e2 = g_pl[j + 2], e3 = g_pl[j + 3];
        float2 a0 = ((const float2*)(g_Xeh + (size_t)e0 * D))[lane];
        float2 a1 = ((const float2*)(g_Xeh + (size_t)e1 * D))[lane];
        float2 a2 = ((const float2*)(g_Xeh + (size_t)e2 * D))[lane];
        float2 a3 = ((const float2*)(g_Xeh + (size_t)e3 * D))[lane];
        acc_h4(acc, a0); acc_h4(acc, a1); acc_h4(acc, a2); acc_h4(acc, a3);
    }
    for (; j < end; j++) {
        float2 a0 = ((const float2*)(g_Xeh + (size_t)g_pl[j] * D))[lane];
        acc_h4(acc, a0);
    }
    float s = (cnt > 0) ? (1.0f / (float)cnt) : 0.f;
    float4 b = *((const float4*)bias + lane);
    float4 r = make_float4(acc.x * s + b.x, acc.y * s + b.y,
                           acc.z * s + b.z, acc.w * s + b.w);
    *((float4*)&out[(size_t)gw * D] + lane) = r;
}

// ---------------- launch ---------------------------------------------------
extern "C" void kernel_launch(void* const* d_in, const int* in_sizes, int n_in,
                              void* d_out, int out_size) {
    const float* input  = (const float*)d_in[0];   // [50000,128]
    const float* weight = (const float*)d_in[1];   // [128,128]
    const float* bias   = (const float*)d_in[2];   // [128]
    const int*   V      = (const int*)d_in[3];     // [800000]
    const int*   E      = (const int*)d_in[4];     // [800000]
    float*       out    = (float*)d_out;           // [50000,128]

    (void)in_sizes; (void)n_in; (void)out_size;

    fused_hist_gemm   <<<HIST_BLOCKS + GEMM_BLOCKS, 128>>>(V, E, input, weight);
    scan_reduce_kernel<<<NBLK, SCAN_BLK>>>();
    scan_apply_kernel <<<NBLK, SCAN_BLK>>>();
    scatter_kernel    <<<(NNZ + 255) / 256, 256>>>(V, E);
    edge_mean_zero_kernel<<<EDGE_BLOCKS + ZERO_BLOCKS, 256>>>();
    node_mean_kernel     <<<NODE_BLOCKS, 256>>>(bias, out);
}

// round 9
// speedup vs baseline: 1.7493x; 1.0783x over previous
#include <cuda_runtime.h>
#include <cuda_fp16.h>
#include <mma.h>

using namespace nvcuda;

#define NUM_NODE 50000
#define NUM_EDGE 25000
#define NNZ      800000
#define D        128
#define NSEG     (NUM_EDGE + NUM_NODE)               // 75000 segments
#define SCAN_BLK 1024
#define NBLK     ((NSEG + SCAN_BLK - 1) / SCAN_BLK)  // 74

#define HIST_BLOCKS 512
#define GEMM_TILES  ((NUM_NODE + 31) / 32)           // 1563 tiles of 32 rows
#define EDGE_BLOCKS (NUM_EDGE / 8)                   // 3125 (8 warps/block)
#define ZERO_BLOCKS ((NSEG + 255) / 256)             // 293
#define NODE_BLOCKS (NUM_NODE / 8)                   // 6250

// ---------------- scratch (static device globals; zero-initialized) -------
__device__ __half g_Xh [NUM_NODE * D];   // input @ weight, fp16 (12.8 MB)
__device__ __half g_Xeh[NUM_EDGE * D];   // edge features, fp16 (6.4 MB)
__device__ int g_cnt[NSEG];              // counts; re-zeroed by edge_mean tail
__device__ int g_off[NSEG + 1];
__device__ int g_bsum[NBLK];
__device__ unsigned int g_rank[NNZ];     // packed ranks: edge lo16 | node hi16
__device__ int g_pl[2 * NNZ];            // CSR payload (partner ids)

// ---------------- GEMM tile role: tf32 wmma, 128 threads, 32 rows ----------
// Block computes X[tile*32 .. +32][0..128] = in @ w via m16n16k8 tf32 MMA.
// 4 warps in a 2x2 (M16 x N64) grid; K tiled by 64 through shared memory.
__device__ __forceinline__ void gemm_tile_role(const float* __restrict__ in,
                                               const float* __restrict__ w,
                                               int tile) {
    __shared__ float ws[64 * D];     // 32 KB: weight K-tile; reused as C staging
    __shared__ float rs[32 * 64];    // 8 KB: input rows K-tile
    int t    = threadIdx.x;
    int warp = t >> 5;
    int row0  = tile * 32;
    int mrow  = (warp & 1) * 16;     // warp's M offset within tile
    int ncol0 = (warp >> 1) * 64;    // warp's N offset

    wmma::fragment<wmma::accumulator, 16, 16, 8, float> acc[4];
    #pragma unroll
    for (int i = 0; i < 4; i++) wmma::fill_fragment(acc[i], 0.0f);

    #pragma unroll
    for (int kt = 0; kt < 2; kt++) {
        __syncthreads();
        // weight[kt*64 .. +64][0..128] -> ws (2048 float4, 16 per thread)
        {
            const float4* src = (const float4*)(w + (size_t)kt * 64 * D);
            float4* dst = (float4*)ws;
            #pragma unroll
            for (int i = 0; i < 16; i++) dst[t + 128 * i] = src[t + 128 * i];
        }
        // input[row0 .. +32][kt*64 .. +64] -> rs (512 float4, 4 per thread, guarded)
        {
            #pragma unroll
            for (int i = 0; i < 4; i++) {
                int idx = t + 128 * i;          // float4 index 0..511
                int r = idx >> 4, c4 = idx & 15;
                int grow = row0 + r;
                float4 v = make_float4(0.f, 0.f, 0.f, 0.f);
                if (grow < NUM_NODE)
                    v = ((const float4*)(in + (size_t)grow * D + kt * 64))[c4];
                ((float4*)&rs[r * 64])[c4] = v;
            }
        }
        __syncthreads();

        #pragma unroll
        for (int ks = 0; ks < 8; ks++) {
            wmma::fragment<wmma::matrix_a, 16, 16, 8, wmma::precision::tf32,
                           wmma::row_major> af;
            wmma::load_matrix_sync(af, &rs[mrow * 64 + ks * 8], 64);
            #pragma unroll
            for (int i = 0; i < af.num_elements; i++)
                af.x[i] = wmma::__float_to_tf32(af.x[i]);
            #pragma unroll
            for (int nf = 0; nf < 4; nf++) {
                wmma::fragment<wmma::matrix_b, 16, 16, 8, wmma::precision::tf32,
                               wmma::row_major> bf;
                wmma::load_matrix_sync(bf, &ws[ks * 8 * D + ncol0 + nf * 16], D);
                #pragma unroll
                for (int i = 0; i < bf.num_elements; i++)
                    bf.x[i] = wmma::__float_to_tf32(bf.x[i]);
                wmma::mma_sync(acc[nf], af, bf, acc[nf]);
            }
        }
    }

    // stage C in ws (32x128 fp32 = 16 KB; weights no longer needed)
    __syncthreads();
    #pragma unroll
    for (int nf = 0; nf < 4; nf++)
        wmma::store_matrix_sync(&ws[mrow * D + ncol0 + nf * 16], acc[nf], D,
                                wmma::mem_row_major);
    __syncthreads();

    // convert to fp16 and write out (2048 half2, 16 per thread, guarded)
    #pragma unroll
    for (int i = 0; i < 16; i++) {
        int idx = t + 128 * i;              // half2 index 0..2047
        int r = idx >> 6, c2 = idx & 63;
        int grow = row0 + r;
        if (grow < NUM_NODE) {
            float2 f = ((const float2*)ws)[idx];
            ((half2*)(g_Xh + (size_t)grow * D))[c2] = __floats2half2_rn(f.x, f.y);
        }
    }
}

// ---------------- L1: hist + ranks | gemm ----------------------------------
__global__ __launch_bounds__(128) void fused_hist_gemm(const int* __restrict__ V,
                                                       const int* __restrict__ E,
                                                       const float* __restrict__ in,
                                                       const float* __restrict__ w) {
    if (blockIdx.x < HIST_BLOCKS) {
        for (int i = blockIdx.x * 128 + threadIdx.x; i < NNZ; i += HIST_BLOCKS * 128) {
            int e = E[i], v = V[i];
            unsigned int re = (unsigned int)atomicAdd(&g_cnt[e], 1);
            unsigned int rv = (unsigned int)atomicAdd(&g_cnt[NUM_EDGE + v], 1);
            g_rank[i] = re | (rv << 16);
        }
    } else {
        gemm_tile_role(in, w, (int)blockIdx.x - HIST_BLOCKS);
    }
}

// ---------------- L2: per-block reduction ----------------------------------
__global__ __launch_bounds__(SCAN_BLK) void scan_reduce_kernel() {
    __shared__ int wsum[32];
    int t = threadIdx.x, lane = t & 31, wid = t >> 5;
    int i = blockIdx.x * SCAN_BLK + t;
    int v = (i < NSEG) ? g_cnt[i] : 0;
    #pragma unroll
    for (int d = 16; d > 0; d >>= 1) v += __shfl_down_sync(0xFFFFFFFFu, v, d);
    if (lane == 0) wsum[wid] = v;
    __syncthreads();
    if (wid == 0) {
        int x = wsum[lane];
        #pragma unroll
        for (int d = 16; d > 0; d >>= 1) x += __shfl_down_sync(0xFFFFFFFFu, x, d);
        if (lane == 0) g_bsum[blockIdx.x] = x;
    }
}

// ---------------- L3: scan + apply with inline block prefix ----------------
__global__ __launch_bounds__(SCAN_BLK) void scan_apply_kernel() {
    __shared__ int wsum[32];
    __shared__ int s_prefix;
    int t = threadIdx.x, lane = t & 31, wid = t >> 5;

    // warp 0 computes this block's global prefix from the 74 block sums
    if (wid == 0) {
        int s = 0;
        for (int i = lane; i < (int)blockIdx.x; i += 32) s += g_bsum[i];
        #pragma unroll
        for (int d = 16; d > 0; d >>= 1) s += __shfl_down_sync(0xFFFFFFFFu, s, d);
        if (lane == 0) s_prefix = s;
    }

    int i = blockIdx.x * SCAN_BLK + t;
    int v = (i < NSEG) ? g_cnt[i] : 0;
    int x = v;
    #pragma unroll
    for (int d = 1; d < 32; d <<= 1) {
        int y = __shfl_up_sync(0xFFFFFFFFu, x, d);
        if (lane >= d) x += y;
    }
    if (lane == 31) wsum[wid] = x;
    __syncthreads();
    if (wid == 0) {
        int wv = wsum[lane];
        #pragma unroll
        for (int d = 1; d < 32; d <<= 1) {
            int y = __shfl_up_sync(0xFFFFFFFFu, wv, d);
            if (lane >= d) wv += y;
        }
        wsum[lane] = wv;
    }
    __syncthreads();
    int warp_excl = (wid == 0) ? 0 : wsum[wid - 1];
    int excl = s_prefix + warp_excl + x - v;
    if (i < NSEG) g_off[i] = excl;
    if (i == NSEG - 1) g_off[NSEG] = excl + v;   // grand total = 2*NNZ
}

// ---------------- L4: rank-based scatter (NO atomics) ----------------------
__global__ void scatter_kernel(const int* __restrict__ V, const int* __restrict__ E) {
    int i = blockIdx.x * blockDim.x + threadIdx.x;
    if (i < NNZ) {
        int e = E[i], v = V[i];
        unsigned int r = g_rank[i];
        g_pl[g_off[e] + (int)(r & 0xFFFFu)] = v;              // edge bucket
        g_pl[g_off[NUM_EDGE + v] + (int)(r >> 16)] = e;       // node bucket
    }
}

// ---------------- fp16 gather helper ---------------------------------------
__device__ __forceinline__ void acc_h4(float4& a, float2 raw) {
    __half2 h01 = *reinterpret_cast<__half2*>(&raw.x);
    __half2 h23 = *reinterpret_cast<__half2*>(&raw.y);
    float2 f01 = __half22float2(h01);
    float2 f23 = __half22float2(h23);
    a.x += f01.x; a.y += f01.y; a.z += f23.x; a.w += f23.y;
}

// ---------------- L5: edge mean (fp16) | zero counts -----------------------
__global__ __launch_bounds__(256) void edge_mean_zero_kernel() {
    if (blockIdx.x < EDGE_BLOCKS) {
        int gw   = blockIdx.x * 8 + (threadIdx.x >> 5);
        int lane = threadIdx.x & 31;
        int start = g_off[gw];
        int end   = g_off[gw + 1];
        int cnt   = end - start;

        float4 acc = make_float4(0.f, 0.f, 0.f, 0.f);
        int j = start;
        for (; j + 4 <= end; j += 4) {
            int n0 = g_pl[j], n1 = g_pl[j + 1];
            int n2 = g_pl[j + 2], n3 = g_pl[j + 3];
            float2 a0 = ((const float2*)(g_Xh + (size_t)n0 * D))[lane];
            float2 a1 = ((const float2*)(g_Xh + (size_t)n1 * D))[lane];
            float2 a2 = ((const float2*)(g_Xh + (size_t)n2 * D))[lane];
            float2 a3 = ((const float2*)(g_Xh + (size_t)n3 * D))[lane];
            acc_h4(acc, a0); acc_h4(acc, a1); acc_h4(acc, a2); acc_h4(acc, a3);
        }
        for (; j < end; j++) {
            float2 a0 = ((const float2*)(g_Xh + (size_t)g_pl[j] * D))[lane];
            acc_h4(acc, a0);
        }
        float s = (cnt > 0) ? (1.0f / (float)cnt) : 0.f;
        __half2 o01 = __floats2half2_rn(acc.x * s, acc.y * s);
        __half2 o23 = __floats2half2_rn(acc.z * s, acc.w * s);
        float2 st;
        *reinterpret_cast<__half2*>(&st.x) = o01;
        *reinterpret_cast<__half2*>(&st.y) = o23;
        ((float2*)(g_Xeh + (size_t)gw * D))[lane] = st;
    } else {
        // re-zero counts for the next graph replay (g_cnt dead after scan)
        int i = (blockIdx.x - EDGE_BLOCKS) * 256 + threadIdx.x;
        if (i < NSEG) g_cnt[i] = 0;
    }
}

// ---------------- L6: node mean (fp16 in) + bias, fp32 out -----------------
__global__ __launch_bounds__(256) void node_mean_kernel(const float* __restrict__ bias,
                                                        float* __restrict__ out) {
    int gw   = blockIdx.x * 8 + (threadIdx.x >> 5);
    int lane = threadIdx.x & 31;
    int start = g_off[NUM_EDGE + gw];
    int end   = g_off[NUM_EDGE + gw + 1];
    int cnt   = end - start;

    float4 acc = make_float4(0.f, 0.f, 0.f, 0.f);
    int j = start;
    for (; j + 4 <= end; j += 4) {
        int e0 = g_pl[j], e1 = g_pl[j + 1];
        int e2 = g_pl[j + 2], e3 = g_pl[j + 3];
        float2 a0 = ((const float2*)(g_Xeh + (size_t)e0 * D))[lane];
        float2 a1 = ((const float2*)(g_Xeh + (size_t)e1 * D))[lane];
        float2 a2 = ((const float2*)(g_Xeh + (size_t)e2 * D))[lane];
        float2 a3 = ((const float2*)(g_Xeh + (size_t)e3 * D))[lane];
        acc_h4(acc, a0); acc_h4(acc, a1); acc_h4(acc, a2); acc_h4(acc, a3);
    }
    for (; j < end; j++) {
        float2 a0 = ((const float2*)(g_Xeh + (size_t)g_pl[j] * D))[lane];
        acc_h4(acc, a0);
    }
    float s = (cnt > 0) ? (1.0f / (float)cnt) : 0.f;
    float4 b = *((const float4*)bias + lane);
    float4 r = make_float4(acc.x * s + b.x, acc.y * s + b.y,
                           acc.z * s + b.z, acc.w * s + b.w);
    *((float4*)&out[(size_t)gw * D] + lane) = r;
}

// ---------------- launch ---------------------------------------------------
extern "C" void kernel_launch(void* const* d_in, const int* in_sizes, int n_in,
                              void* d_out, int out_size) {
    const float* input  = (const float*)d_in[0];   // [50000,128]
    const float* weight = (const float*)d_in[1];   // [128,128]
    const float* bias   = (const float*)d_in[2];   // [128]
    const int*   V      = (const int*)d_in[3];     // [800000]
    const int*   E      = (const int*)d_in[4];     // [800000]
    float*       out    = (float*)d_out;           // [50000,128]

    (void)in_sizes; (void)n_in; (void)out_size;

    fused_hist_gemm   <<<HIST_BLOCKS + GEMM_TILES, 128>>>(V, E, input, weight);
    scan_reduce_kernel<<<NBLK, SCAN_BLK>>>();
    scan_apply_kernel <<<NBLK, SCAN_BLK>>>();
    scatter_kernel    <<<(NNZ + 255) / 256, 256>>>(V, E);
    edge_mean_zero_kernel<<<EDGE_BLOCKS + ZERO_BLOCKS, 256>>>();
    node_mean_kernel     <<<NODE_BLOCKS, 256>>>(bias, out);
}

// round 10
// speedup vs baseline: 1.7498x; 1.0002x over previous
#include <cuda_runtime.h>
#include <cuda_fp16.h>
#include <mma.h>

using namespace nvcuda;

#define NUM_NODE 50000
#define NUM_EDGE 25000
#define NNZ      800000
#define D        128
#define NSEG     (NUM_EDGE + NUM_NODE)               // 75000 segments
#define SCAN_BLK 1024
#define NBLK     ((NSEG + SCAN_BLK - 1) / SCAN_BLK)  // 74

#define HIST_BLOCKS 512
#define GEMM_TILES  ((NUM_NODE + 31) / 32)           // 1563 tiles of 32 rows
#define EDGE_BLOCKS (NUM_EDGE / 8)                   // 3125 (8 warps/block)
#define SCATN_BLOCKS 1024                            // node-bucket scatter role
#define ZERO_BLOCKS ((NSEG + 255) / 256)             // 293
#define NODE_BLOCKS (NUM_NODE / 8)                   // 6250

// ---------------- scratch (static device globals; zero-initialized) -------
__device__ __half g_Xh [NUM_NODE * D];   // input @ weight, fp16 (12.8 MB)
__device__ __half g_Xeh[NUM_EDGE * D];   // edge features, fp16 (6.4 MB)
__device__ int g_cnt[NSEG];              // counts; re-zeroed by edge_mean tail
__device__ int g_off[NSEG + 1];
__device__ int g_bsum[NBLK];
__device__ unsigned int g_rank[NNZ];     // packed ranks: edge lo16 | node hi16
__device__ int g_pl[2 * NNZ];            // CSR payload (partner ids)

// ---------------- GEMM tile role: tf32 wmma, 128 threads, 32 rows ----------
// K tiled by 32 -> 20 KB static smem (ws 16 KB + rs 4 KB) so hist blocks in
// the same launch keep high co-residency. C stages in ws after the last tile.
__device__ __forceinline__ void gemm_tile_role(const float* __restrict__ in,
                                               const float* __restrict__ w,
                                               int tile) {
    __shared__ float ws[32 * D];     // 16 KB: weight K-tile; reused as C staging
    __shared__ float rs[32 * 32];    // 4 KB: input rows K-tile
    int t    = threadIdx.x;
    int warp = t >> 5;
    int row0  = tile * 32;
    int mrow  = (warp & 1) * 16;     // warp's M offset within tile
    int ncol0 = (warp >> 1) * 64;    // warp's N offset

    wmma::fragment<wmma::accumulator, 16, 16, 8, float> acc[4];
    #pragma unroll
    for (int i = 0; i < 4; i++) wmma::fill_fragment(acc[i], 0.0f);

    #pragma unroll
    for (int kt = 0; kt < 4; kt++) {
        __syncthreads();
        // weight[kt*32 .. +32][0..128] -> ws (1024 float4, 8 per thread)
        {
            const float4* src = (const float4*)(w + (size_t)kt * 32 * D);
            float4* dst = (float4*)ws;
            #pragma unroll
            for (int i = 0; i < 8; i++) dst[t + 128 * i] = src[t + 128 * i];
        }
        // input[row0 .. +32][kt*32 .. +32] -> rs (256 float4, 2 per thread, guarded)
        {
            #pragma unroll
            for (int i = 0; i < 2; i++) {
                int idx = t + 128 * i;          // float4 index 0..255
                int r = idx >> 3, c4 = idx & 7;
                int grow = row0 + r;
                float4 v = make_float4(0.f, 0.f, 0.f, 0.f);
                if (grow < NUM_NODE)
                    v = ((const float4*)(in + (size_t)grow * D + kt * 32))[c4];
                ((float4*)&rs[r * 32])[c4] = v;
            }
        }
        __syncthreads();

        #pragma unroll
        for (int ks = 0; ks < 4; ks++) {
            wmma::fragment<wmma::matrix_a, 16, 16, 8, wmma::precision::tf32,
                           wmma::row_major> af;
            wmma::load_matrix_sync(af, &rs[mrow * 32 + ks * 8], 32);
            #pragma unroll
            for (int i = 0; i < af.num_elements; i++)
                af.x[i] = wmma::__float_to_tf32(af.x[i]);
            #pragma unroll
            for (int nf = 0; nf < 4; nf++) {
                wmma::fragment<wmma::matrix_b, 16, 16, 8, wmma::precision::tf32,
                               wmma::row_major> bf;
                wmma::load_matrix_sync(bf, &ws[ks * 8 * D + ncol0 + nf * 16], D);
                #pragma unroll
                for (int i = 0; i < bf.num_elements; i++)
                    bf.x[i] = wmma::__float_to_tf32(bf.x[i]);
                wmma::mma_sync(acc[nf], af, bf, acc[nf]);
            }
        }
    }

    // stage C in ws (32x128 fp32 = 16 KB; weights no longer needed)
    __syncthreads();
    #pragma unroll
    for (int nf = 0; nf < 4; nf++)
        wmma::store_matrix_sync(&ws[mrow * D + ncol0 + nf * 16], acc[nf], D,
                                wmma::mem_row_major);
    __syncthreads();

    // convert to fp16 and write out (2048 half2, 16 per thread, guarded)
    #pragma unroll
    for (int i = 0; i < 16; i++) {
        int idx = t + 128 * i;              // half2 index 0..2047
        int r = idx >> 6, c2 = idx & 63;
        int grow = row0 + r;
        if (grow < NUM_NODE) {
            float2 f = ((const float2*)ws)[idx];
            ((half2*)(g_Xh + (size_t)grow * D))[c2] = __floats2half2_rn(f.x, f.y);
        }
    }
}

// ---------------- L1: hist + ranks | gemm ----------------------------------
__global__ __launch_bounds__(128) void fused_hist_gemm(const int* __restrict__ V,
                                                       const int* __restrict__ E,
                                                       const float* __restrict__ in,
                                                       const float* __restrict__ w) {
    if (blockIdx.x < HIST_BLOCKS) {
        for (int i = blockIdx.x * 128 + threadIdx.x; i < NNZ; i += HIST_BLOCKS * 128) {
            int e = E[i], v = V[i];
            unsigned int re = (unsigned int)atomicAdd(&g_cnt[e], 1);
            unsigned int rv = (unsigned int)atomicAdd(&g_cnt[NUM_EDGE + v], 1);
            g_rank[i] = re | (rv << 16);
        }
    } else {
        gemm_tile_role(in, w, (int)blockIdx.x - HIST_BLOCKS);
    }
}

// ---------------- L2: per-block reduction ----------------------------------
__global__ __launch_bounds__(SCAN_BLK) void scan_reduce_kernel() {
    __shared__ int wsum[32];
    int t = threadIdx.x, lane = t & 31, wid = t >> 5;
    int i = blockIdx.x * SCAN_BLK + t;
    int v = (i < NSEG) ? g_cnt[i] : 0;
    #pragma unroll
    for (int d = 16; d > 0; d >>= 1) v += __shfl_down_sync(0xFFFFFFFFu, v, d);
    if (lane == 0) wsum[wid] = v;
    __syncthreads();
    if (wid == 0) {
        int x = wsum[lane];
        #pragma unroll
        for (int d = 16; d > 0; d >>= 1) x += __shfl_down_sync(0xFFFFFFFFu, x, d);
        if (lane == 0) g_bsum[blockIdx.x] = x;
    }
}

// ---------------- L3: scan + apply with inline block prefix ----------------
__global__ __launch_bounds__(SCAN_BLK) void scan_apply_kernel() {
    __shared__ int wsum[32];
    __shared__ int s_prefix;
    int t = threadIdx.x, lane = t & 31, wid = t >> 5;

    if (wid == 0) {
        int s = 0;
        for (int i = lane; i < (int)blockIdx.x; i += 32) s += g_bsum[i];
        #pragma unroll
        for (int d = 16; d > 0; d >>= 1) s += __shfl_down_sync(0xFFFFFFFFu, s, d);
        if (lane == 0) s_prefix = s;
    }

    int i = blockIdx.x * SCAN_BLK + t;
    int v = (i < NSEG) ? g_cnt[i] : 0;
    int x = v;
    #pragma unroll
    for (int d = 1; d < 32; d <<= 1) {
        int y = __shfl_up_sync(0xFFFFFFFFu, x, d);
        if (lane >= d) x += y;
    }
    if (lane == 31) wsum[wid] = x;
    __syncthreads();
    if (wid == 0) {
        int wv = wsum[lane];
        #pragma unroll
        for (int d = 1; d < 32; d <<= 1) {
            int y = __shfl_up_sync(0xFFFFFFFFu, wv, d);
            if (lane >= d) wv += y;
        }
        wsum[lane] = wv;
    }
    __syncthreads();
    int warp_excl = (wid == 0) ? 0 : wsum[wid - 1];
    int excl = s_prefix + warp_excl + x - v;
    if (i < NSEG) g_off[i] = excl;
    if (i == NSEG - 1) g_off[NSEG] = excl + v;   // grand total = 2*NNZ
}

// ---------------- L4: edge-bucket scatter only (node buckets deferred) -----
__global__ void scatter_edge_kernel(const int* __restrict__ V,
                                    const int* __restrict__ E) {
    int i = blockIdx.x * blockDim.x + threadIdx.x;
    if (i < NNZ) {
        unsigned int r = g_rank[i];
        g_pl[g_off[E[i]] + (int)(r & 0xFFFFu)] = V[i];        // edge bucket
    }
}

// ---------------- fp16 gather helper ---------------------------------------
__device__ __forceinline__ void acc_h4(float4& a, float2 raw) {
    __half2 h01 = *reinterpret_cast<__half2*>(&raw.x);
    __half2 h23 = *reinterpret_cast<__half2*>(&raw.y);
    float2 f01 = __half22float2(h01);
    float2 f23 = __half22float2(h23);
    a.x += f01.x; a.y += f01.y; a.z += f23.x; a.w += f23.y;
}

// ---------------- L5: edge mean | node-bucket scatter | zero counts --------
__global__ __launch_bounds__(256) void edge_mean_scatn_zero_kernel(
        const int* __restrict__ V, const int* __restrict__ E) {
    if (blockIdx.x < EDGE_BLOCKS) {
        int gw   = blockIdx.x * 8 + (threadIdx.x >> 5);
        int lane = threadIdx.x & 31;
        int start = g_off[gw];
        int end   = g_off[gw + 1];
        int cnt   = end - start;

        float4 acc = make_float4(0.f, 0.f, 0.f, 0.f);
        int j = start;
        for (; j + 4 <= end; j += 4) {
            int n0 = g_pl[j], n1 = g_pl[j + 1];
            int n2 = g_pl[j + 2], n3 = g_pl[j + 3];
            float2 a0 = ((const float2*)(g_Xh + (size_t)n0 * D))[lane];
            float2 a1 = ((const float2*)(g_Xh + (size_t)n1 * D))[lane];
            float2 a2 = ((const float2*)(g_Xh + (size_t)n2 * D))[lane];
            float2 a3 = ((const float2*)(g_Xh + (size_t)n3 * D))[lane];
            acc_h4(acc, a0); acc_h4(acc, a1); acc_h4(acc, a2); acc_h4(acc, a3);
        }
        for (; j < end; j++) {
            float2 a0 = ((const float2*)(g_Xh + (size_t)g_pl[j] * D))[lane];
            acc_h4(acc, a0);
        }
        float s = (cnt > 0) ? (1.0f / (float)cnt) : 0.f;
        __half2 o01 = __floats2half2_rn(acc.x * s, acc.y * s);
        __half2 o23 = __floats2half2_rn(acc.z * s, acc.w * s);
        float2 st;
        *reinterpret_cast<__half2*>(&st.x) = o01;
        *reinterpret_cast<__half2*>(&st.y) = o23;
        ((float2*)(g_Xeh + (size_t)gw * D))[lane] = st;
    } else if (blockIdx.x < EDGE_BLOCKS + SCATN_BLOCKS) {
        // node-bucket scatter (needed only by node_mean, next launch)
        int b = blockIdx.x - EDGE_BLOCKS;
        for (int i = b * 256 + threadIdx.x; i < NNZ; i += SCATN_BLOCKS * 256) {
            unsigned int r = g_rank[i];
            g_pl[g_off[NUM_EDGE + V[i]] + (int)(r >> 16)] = E[i];
        }
    } else {
        // re-zero counts for the next graph replay (g_cnt dead after scan)
        int i = (blockIdx.x - EDGE_BLOCKS - SCATN_BLOCKS) * 256 + threadIdx.x;
        if (i < NSEG) g_cnt[i] = 0;
    }
}

// ---------------- L6: node mean (fp16 in) + bias, fp32 out -----------------
__global__ __launch_bounds__(256) void node_mean_kernel(const float* __restrict__ bias,
                                                        float* __restrict__ out) {
    int gw   = blockIdx.x * 8 + (threadIdx.x >> 5);
    int lane = threadIdx.x & 31;
    int start = g_off[NUM_EDGE + gw];
    int end   = g_off[NUM_EDGE + gw + 1];
    int cnt   = end - start;

    float4 acc = make_float4(0.f, 0.f, 0.f, 0.f);
    int j = start;
    for (; j + 4 <= end; j += 4) {
        int e0 = g_pl[j], e1 = g_pl[j + 1];
        int e2 = g_pl[j + 2], e3 = g_pl[j + 3];
        float2 a0 = ((const float2*)(g_Xeh + (size_t)e0 * D))[lane];
        float2 a1 = ((const float2*)(g_Xeh + (size_t)e1 * D))[lane];
        float2 a2 = ((const float2*)(g_Xeh + (size_t)e2 * D))[lane];
        float2 a3 = ((const float2*)(g_Xeh + (size_t)e3 * D))[lane];
        acc_h4(acc, a0); acc_h4(acc, a1); acc_h4(acc, a2); acc_h4(acc, a3);
    }
    for (; j < end; j++) {
        float2 a0 = ((const float2*)(g_Xeh + (size_t)g_pl[j] * D))[lane];
        acc_h4(acc, a0);
    }
    float s = (cnt > 0) ? (1.0f / (float)cnt) : 0.f;
    float4 b = *((const float4*)bias + lane);
    float4 r = make_float4(acc.x * s + b.x, acc.y * s + b.y,
                           acc.z * s + b.z, acc.w * s + b.w);
    *((float4*)&out[(size_t)gw * D] + lane) = r;
}

// ---------------- launch ---------------------------------------------------
extern "C" void kernel_launch(void* const* d_in, const int* in_sizes, int n_in,
                              void* d_out, int out_size) {
    const float* input  = (const float*)d_in[0];   // [50000,128]
    const float* weight = (const float*)d_in[1];   // [128,128]
    const float* bias   = (const float*)d_in[2];   // [128]
    const int*   V      = (const int*)d_in[3];     // [800000]
    const int*   E      = (const int*)d_in[4];     // [800000]
    float*       out    = (float*)d_out;           // [50000,128]

    (void)in_sizes; (void)n_in; (void)out_size;

    fused_hist_gemm    <<<HIST_BLOCKS + GEMM_TILES, 128>>>(V, E, input, weight);
    scan_reduce_kernel <<<NBLK, SCAN_BLK>>>();
    scan_apply_kernel  <<<NBLK, SCAN_BLK>>>();
    scatter_edge_kernel<<<(NNZ + 255) / 256, 256>>>(V, E);
    edge_mean_scatn_zero_kernel<<<EDGE_BLOCKS + SCATN_BLOCKS + ZERO_BLOCKS, 256>>>(V, E);
    node_mean_kernel   <<<NODE_BLOCKS, 256>>>(bias, out);
}

// round 11
// speedup vs baseline: 2.4336x; 1.3908x over previous
#include <cuda_runtime.h>
#include <cuda_fp16.h>
#include <mma.h>

using namespace nvcuda;

#define NUM_NODE 50000
#define NUM_EDGE 25000
#define NNZ      800000
#define D        128
#define NSEG     (NUM_EDGE + NUM_NODE)               // 75000 segments
#define SCAN_BLK 1024
#define NBLK     ((NSEG + SCAN_BLK - 1) / SCAN_BLK)  // 74

#define HIST_BLOCKS 512
#define GEMM_TILES  ((NUM_NODE + 31) / 32)           // 1563 tiles of 32 rows
#define EDGE_BLOCKS (NUM_EDGE / 8)                   // 3125 (8 warps/block)
#define SCATN_BLOCKS 1024                            // node-bucket scatter role
#define ZERO_BLOCKS ((NSEG + 255) / 256)             // 293
#define NODE_BLOCKS (NUM_NODE / 8)                   // 6250

#define WPAD 136                                     // padded half row (ws)
#define RPAD 72                                      // padded half row (rs)

// ---------------- scratch (static device globals; zero-initialized) -------
__device__ __half g_Xh [NUM_NODE * D];   // input @ weight, fp16 (12.8 MB)
__device__ __half g_Xeh[NUM_EDGE * D];   // edge features, fp16 (6.4 MB)
__device__ int g_cnt[NSEG];              // counts; re-zeroed by edge_mean tail
__device__ int g_off[NSEG + 1];
__device__ int g_bsum[NBLK];
__device__ unsigned int g_rank[NNZ];     // packed ranks: edge lo16 | node hi16
__device__ int g_pl[2 * NNZ];            // CSR payload (partner ids)

// ---------------- GEMM tile role: fp16 wmma m16n16k16, 128 thr, 32 rows ----
// Inputs converted to half ONCE at smem fill; padded rows kill bank conflicts.
// 4 warps in 2x2 (M16 x N64); K tiled by 64; fp32 accumulate.
__device__ __forceinline__ void gemm_tile_role(const float* __restrict__ in,
                                               const float* __restrict__ w,
                                               int tile) {
    __shared__ __align__(16) __half ws[64 * WPAD];   // 17.4 KB weight K-tile
    __shared__ __align__(16) __half rs[32 * RPAD];   // 4.6 KB input K-tile
    __shared__ __align__(16) float  cs[4][16 * 16];  // 4 KB per-warp C staging
    int t    = threadIdx.x;
    int warp = t >> 5;
    int lane = t & 31;
    int row0  = tile * 32;
    int mrow  = (warp & 1) * 16;     // warp's M offset within tile
    int ncol0 = (warp >> 1) * 64;    // warp's N offset

    wmma::fragment<wmma::accumulator, 16, 16, 16, float> acc[4];
    #pragma unroll
    for (int i = 0; i < 4; i++) wmma::fill_fragment(acc[i], 0.0f);

    #pragma unroll
    for (int kt = 0; kt < 2; kt++) {
        __syncthreads();
        // weight[kt*64 .. +64][0..128] fp32 -> half into ws (padded rows)
        {
            const float4* src = (const float4*)(w + (size_t)kt * 64 * D);
            #pragma unroll
            for (int i = 0; i < 16; i++) {
                int idx = t + 128 * i;          // float4 idx 0..2047
                int r = idx >> 5, c4 = idx & 31;
                float4 v = src[r * 32 + c4];
                half2 h0 = __floats2half2_rn(v.x, v.y);
                half2 h1 = __floats2half2_rn(v.z, v.w);
                *(half2*)&ws[r * WPAD + c4 * 4]     = h0;
                *(half2*)&ws[r * WPAD + c4 * 4 + 2] = h1;
            }
        }
        // input[row0 .. +32][kt*64 .. +64] fp32 -> half into rs (guarded)
        {
            #pragma unroll
            for (int i = 0; i < 4; i++) {
                int idx = t + 128 * i;          // float4 idx 0..511
                int r = idx >> 4, c4 = idx & 15;
                int grow = row0 + r;
                float4 v = make_float4(0.f, 0.f, 0.f, 0.f);
                if (grow < NUM_NODE)
                    v = ((const float4*)(in + (size_t)grow * D + kt * 64))[c4];
                half2 h0 = __floats2half2_rn(v.x, v.y);
                half2 h1 = __floats2half2_rn(v.z, v.w);
                *(half2*)&rs[r * RPAD + c4 * 4]     = h0;
                *(half2*)&rs[r * RPAD + c4 * 4 + 2] = h1;
            }
        }
        __syncthreads();

        #pragma unroll
        for (int ks = 0; ks < 4; ks++) {
            wmma::fragment<wmma::matrix_a, 16, 16, 16, __half, wmma::row_major> af;
            wmma::load_matrix_sync(af, &rs[mrow * RPAD + ks * 16], RPAD);
            #pragma unroll
            for (int nf = 0; nf < 4; nf++) {
                wmma::fragment<wmma::matrix_b, 16, 16, 16, __half, wmma::row_major> bf;
                wmma::load_matrix_sync(bf, &ws[ks * 16 * WPAD + ncol0 + nf * 16], WPAD);
                wmma::mma_sync(acc[nf], af, bf, acc[nf]);
            }
        }
    }

    // per-warp C staging -> fp16 gmem (guarded)
    #pragma unroll
    for (int nf = 0; nf < 4; nf++) {
        wmma::store_matrix_sync(&cs[warp][0], acc[nf], 16, wmma::mem_row_major);
        __syncwarp();
        #pragma unroll
        for (int j = 0; j < 4; j++) {
            int h = lane + 32 * j;              // half2 idx 0..127 within 16x16
            int r = h >> 3, c2 = h & 7;
            int grow = row0 + mrow + r;
            if (grow < NUM_NODE) {
                float2 f = ((const float2*)&cs[warp][0])[h];
                ((half2*)(g_Xh + (size_t)grow * D))[(ncol0 + nf * 16) / 2 + c2] =
                    __floats2half2_rn(f.x, f.y);
            }
        }
        __syncwarp();
    }
}

// ---------------- L1: hist + ranks | gemm ----------------------------------
__global__ __launch_bounds__(128) void fused_hist_gemm(const int* __restrict__ V,
                                                       const int* __restrict__ E,
                                                       const float* __restrict__ in,
                                                       const float* __restrict__ w) {
    if (blockIdx.x < HIST_BLOCKS) {
        for (int i = blockIdx.x * 128 + threadIdx.x; i < NNZ; i += HIST_BLOCKS * 128) {
            int e = E[i], v = V[i];
            unsigned int re = (unsigned int)atomicAdd(&g_cnt[e], 1);
            unsigned int rv = (unsigned int)atomicAdd(&g_cnt[NUM_EDGE + v], 1);
            g_rank[i] = re | (rv << 16);
        }
    } else {
        gemm_tile_role(in, w, (int)blockIdx.x - HIST_BLOCKS);
    }
}

// ---------------- L2: per-block reduction ----------------------------------
__global__ __launch_bounds__(SCAN_BLK) void scan_reduce_kernel() {
    __shared__ int wsum[32];
    int t = threadIdx.x, lane = t & 31, wid = t >> 5;
    int i = blockIdx.x * SCAN_BLK + t;
    int v = (i < NSEG) ? g_cnt[i] : 0;
    #pragma unroll
    for (int d = 16; d > 0; d >>= 1) v += __shfl_down_sync(0xFFFFFFFFu, v, d);
    if (lane == 0) wsum[wid] = v;
    __syncthreads();
    if (wid == 0) {
        int x = wsum[lane];
        #pragma unroll
        for (int d = 16; d > 0; d >>= 1) x += __shfl_down_sync(0xFFFFFFFFu, x, d);
        if (lane == 0) g_bsum[blockIdx.x] = x;
    }
}

// ---------------- L3: scan + apply with inline block prefix ----------------
__global__ __launch_bounds__(SCAN_BLK) void scan_apply_kernel() {
    __shared__ int wsum[32];
    __shared__ int s_prefix;
    int t = threadIdx.x, lane = t & 31, wid = t >> 5;

    if (wid == 0) {
        int s = 0;
        for (int i = lane; i < (int)blockIdx.x; i += 32) s += g_bsum[i];
        #pragma unroll
        for (int d = 16; d > 0; d >>= 1) s += __shfl_down_sync(0xFFFFFFFFu, s, d);
        if (lane == 0) s_prefix = s;
    }

    int i = blockIdx.x * SCAN_BLK + t;
    int v = (i < NSEG) ? g_cnt[i] : 0;
    int x = v;
    #pragma unroll
    for (int d = 1; d < 32; d <<= 1) {
        int y = __shfl_up_sync(0xFFFFFFFFu, x, d);
        if (lane >= d) x += y;
    }
    if (lane == 31) wsum[wid] = x;
    __syncthreads();
    if (wid == 0) {
        int wv = wsum[lane];
        #pragma unroll
        for (int d = 1; d < 32; d <<= 1) {
            int y = __shfl_up_sync(0xFFFFFFFFu, wv, d);
            if (lane >= d) wv += y;
        }
        wsum[lane] = wv;
    }
    __syncthreads();
    int warp_excl = (wid == 0) ? 0 : wsum[wid - 1];
    int excl = s_prefix + warp_excl + x - v;
    if (i < NSEG) g_off[i] = excl;
    if (i == NSEG - 1) g_off[NSEG] = excl + v;   // grand total = 2*NNZ
}

// ---------------- L4: edge-bucket scatter only (node buckets deferred) -----
__global__ void scatter_edge_kernel(const int* __restrict__ V,
                                    const int* __restrict__ E) {
    int i = blockIdx.x * blockDim.x + threadIdx.x;
    if (i < NNZ) {
        unsigned int r = g_rank[i];
        g_pl[g_off[E[i]] + (int)(r & 0xFFFFu)] = V[i];        // edge bucket
    }
}

// ---------------- fp16 gather helper ---------------------------------------
__device__ __forceinline__ void acc_h4(float4& a, float2 raw) {
    __half2 h01 = *reinterpret_cast<__half2*>(&raw.x);
    __half2 h23 = *reinterpret_cast<__half2*>(&raw.y);
    float2 f01 = __half22float2(h01);
    float2 f23 = __half22float2(h23);
    a.x += f01.x; a.y += f01.y; a.z += f23.x; a.w += f23.y;
}

// ---------------- L5: edge mean | node-bucket scatter | zero counts --------
__global__ __launch_bounds__(256) void edge_mean_scatn_zero_kernel(
        const int* __restrict__ V, const int* __restrict__ E) {
    if (blockIdx.x < EDGE_BLOCKS) {
        int gw   = blockIdx.x * 8 + (threadIdx.x >> 5);
        int lane = threadIdx.x & 31;
        int start = g_off[gw];
        int end   = g_off[gw + 1];
        int cnt   = end - start;

        float4 acc = make_float4(0.f, 0.f, 0.f, 0.f);
        int j = start;
        for (; j + 4 <= end; j += 4) {
            int n0 = g_pl[j], n1 = g_pl[j + 1];
            int n2 = g_pl[j + 2], n3 = g_pl[j + 3];
            float2 a0 = ((const float2*)(g_Xh + (size_t)n0 * D))[lane];
            float2 a1 = ((const float2*)(g_Xh + (size_t)n1 * D))[lane];
            float2 a2 = ((const float2*)(g_Xh + (size_t)n2 * D))[lane];
            float2 a3 = ((const float2*)(g_Xh + (size_t)n3 * D))[lane];
            acc_h4(acc, a0); acc_h4(acc, a1); acc_h4(acc, a2); acc_h4(acc, a3);
        }
        for (; j < end; j++) {
            float2 a0 = ((const float2*)(g_Xh + (size_t)g_pl[j] * D))[lane];
            acc_h4(acc, a0);
        }
        float s = (cnt > 0) ? (1.0f / (float)cnt) : 0.f;
        __half2 o01 = __floats2half2_rn(acc.x * s, acc.y * s);
        __half2 o23 = __floats2half2_rn(acc.z * s, acc.w * s);
        float2 st;
        *reinterpret_cast<__half2*>(&st.x) = o01;
        *reinterpret_cast<__half2*>(&st.y) = o23;
        ((float2*)(g_Xeh + (size_t)gw * D))[lane] = st;
    } else if (blockIdx.x < EDGE_BLOCKS + SCATN_BLOCKS) {
        // node-bucket scatter (needed only by node_mean, next launch)
        int b = blockIdx.x - EDGE_BLOCKS;
        for (int i = b * 256 + threadIdx.x; i < NNZ; i += SCATN_BLOCKS * 256) {
            unsigned int r = g_rank[i];
            g_pl[g_off[NUM_EDGE + V[i]] + (int)(r >> 16)] = E[i];
        }
    } else {
        // re-zero counts for the next graph replay (g_cnt dead after scan)
        int i = (blockIdx.x - EDGE_BLOCKS - SCATN_BLOCKS) * 256 + threadIdx.x;
        if (i < NSEG) g_cnt[i] = 0;
    }
}

// ---------------- L6: node mean (fp16 in) + bias, fp32 out -----------------
__global__ __launch_bounds__(256) void node_mean_kernel(const float* __restrict__ bias,
                                                        float* __restrict__ out) {
    int gw   = blockIdx.x * 8 + (threadIdx.x >> 5);
    int lane = threadIdx.x & 31;
    int start = g_off[NUM_EDGE + gw];
    int end   = g_off[NUM_EDGE + gw + 1];
    int cnt   = end - start;

    float4 acc = make_float4(0.f, 0.f, 0.f, 0.f);
    int j = start;
    for (; j + 4 <= end; j += 4) {
        int e0 = g_pl[j], e1 = g_pl[j + 1];
        int e2 = g_pl[j + 2], e3 = g_pl[j + 3];
        float2 a0 = ((const float2*)(g_Xeh + (size_t)e0 * D))[lane];
        float2 a1 = ((const float2*)(g_Xeh + (size_t)e1 * D))[lane];
        float2 a2 = ((const float2*)(g_Xeh + (size_t)e2 * D))[lane];
        float2 a3 = ((const float2*)(g_Xeh + (size_t)e3 * D))[lane];
        acc_h4(acc, a0); acc_h4(acc, a1); acc_h4(acc, a2); acc_h4(acc, a3);
    }
    for (; j < end; j++) {
        float2 a0 = ((const float2*)(g_Xeh + (size_t)g_pl[j] * D))[lane];
        acc_h4(acc, a0);
    }
    float s = (cnt > 0) ? (1.0f / (float)cnt) : 0.f;
    float4 b = *((const float4*)bias + lane);
    float4 r = make_float4(acc.x * s + b.x, acc.y * s + b.y,
                           acc.z * s + b.z, acc.w * s + b.w);
    *((float4*)&out[(size_t)gw * D] + lane) = r;
}

// ---------------- launch ---------------------------------------------------
extern "C" void kernel_launch(void* const* d_in, const int* in_sizes, int n_in,
                              void* d_out, int out_size) {
    const float* input  = (const float*)d_in[0];   // [50000,128]
    const float* weight = (const float*)d_in[1];   // [128,128]
    const float* bias   = (const float*)d_in[2];   // [128]
    const int*   V      = (const int*)d_in[3];     // [800000]
    const int*   E      = (const int*)d_in[4];     // [800000]
    float*       out    = (float*)d_out;           // [50000,128]

    (void)in_sizes; (void)n_in; (void)out_size;

    fused_hist_gemm    <<<HIST_BLOCKS + GEMM_TILES, 128>>>(V, E, input, weight);
    scan_reduce_kernel <<<NBLK, SCAN_BLK>>>();
    scan_apply_kernel  <<<NBLK, SCAN_BLK>>>();
    scatter_edge_kernel<<<(NNZ + 255) / 256, 256>>>(V, E);
    edge_mean_scatn_zero_kernel<<<EDGE_BLOCKS + SCATN_BLOCKS + ZERO_BLOCKS, 256>>>(V, E);
    node_mean_kernel   <<<NODE_BLOCKS, 256>>>(bias, out);
}